// round 12
// baseline (speedup 1.0000x reference)
#include <cuda_runtime.h>
#include <math.h>

#define B_    32
#define NIN   2312
#define NHID  512
#define NOUT  10
#define T_    350
#define TK    100
#define THETA 10.0f

// refractory IIR constants
#define D_REF 0.36787944117144233f
#define C_REF (-5.43656365691809f)

// psp alpha-kernel IIR constants: eps[k] = (e/10) * k * d^k, d = e^{-0.1}
#define D_SR  0.90483741803595952f    // exp(-0.1)
#define C_E   0.27182818284590452f    // e/10
#define K2C   1.2340980408667956e-05f // C_E * exp(-10)
#define K3C   1.2340980408667956e-03f // 100 * C_E * exp(-10)

// sparse index structure
#define NCH   8
#define CHUNK 289
#define CAPC  96
#define NCOL  (B_ * T_)           // 11200

#define R1    (B_ * NHID)         // 16384
#define R2    (B_ * NOUT)         // 320

// ------------------------- static device scratch ---------------------------
__device__ float g_W1T[(size_t)NIN * NHID];                 // [i, o]
__device__ unsigned short g_idx[(size_t)NCOL * NCH * CAPC];
__device__ int            g_cnt[(size_t)NCOL * NCH];
__device__ float g_y1[(size_t)T_ * R1];   // t-major: [t][b*512+o]
__device__ float g_s1[(size_t)T_ * R1];   // t-major
__device__ float g_z2[(size_t)T_ * R2];   // t-major

// ---------------------------------------------------------------------------
// Tiled transpose: W1T[i*512 + o] = W1[o*2312 + i]
// ---------------------------------------------------------------------------
__global__ __launch_bounds__(256) void transpose_w1_kernel(const float* __restrict__ W1) {
    __shared__ float tile[32][33];
    const int i0 = blockIdx.x * 32;
    const int o0 = blockIdx.y * 32;
    const int lx = threadIdx.x & 31;
    const int ly = threadIdx.x >> 5;

#pragma unroll
    for (int r = 0; r < 32; r += 8) {
        int o = o0 + ly + r;
        int i = i0 + lx;
        tile[ly + r][lx] = (i < NIN) ? W1[(size_t)o * NIN + i] : 0.0f;
    }
    __syncthreads();
#pragma unroll
    for (int r = 0; r < 32; r += 8) {
        int i = i0 + ly + r;
        int o = o0 + lx;
        if (i < NIN) g_W1T[(size_t)i * NHID + o] = tile[lx][ly + r];
    }
}

// ---------------------------------------------------------------------------
// Build per-(b,t,chunk) lists of active input indices (coalesced over t).
// ---------------------------------------------------------------------------
__global__ __launch_bounds__(128) void build_idx_kernel(const float* __restrict__ X) {
    const int t = blockIdx.x * 128 + threadIdx.x;
    const int c = blockIdx.y;
    const int b = blockIdx.z;
    if (t >= T_) return;

    const int col = b * T_ + t;
    unsigned short* dst = g_idx + ((size_t)col * NCH + c) * CAPC;
    const float* __restrict__ xb = X + (size_t)b * NIN * T_ + t;

    int cnt = 0;
    const int i0 = c * CHUNK;
#pragma unroll 4
    for (int i = i0; i < i0 + CHUNK; i++) {
        float v = xb[(size_t)i * T_];
        if (v != 0.0f) {
            if (cnt < CAPC) dst[cnt] = (unsigned short)i;
            cnt++;
        }
    }
    g_cnt[col * NCH + c] = (cnt < CAPC) ? cnt : CAPC;
}

// ---------------------------------------------------------------------------
// Sparse gather-accumulate (proven at the L2 roofline):
//   y1T[t][b*512 + :] = sum_{i active(b,t)} W1T[i,:]
// One block per (b,t) column; 128 threads x float4 = 512 outputs.
// ---------------------------------------------------------------------------
__global__ __launch_bounds__(128) void sparse_accum_kernel() {
    const int col = blockIdx.x;
    const int tid = threadIdx.x;

    __shared__ unsigned short sidx[NCH * CAPC];
    __shared__ int psum[NCH + 1];

    if (tid == 0) {
        int s = 0;
        psum[0] = 0;
#pragma unroll
        for (int c = 0; c < NCH; c++) { s += g_cnt[col * NCH + c]; psum[c + 1] = s; }
    }
    __syncthreads();

    if (tid < NCH) {
        const int c = tid;
        const int n = psum[c + 1] - psum[c];
        const unsigned short* src = g_idx + ((size_t)col * NCH + c) * CAPC;
        unsigned short* d = sidx + psum[c];
        for (int k = 0; k < n; k++) d[k] = src[k];
    }
    __syncthreads();

    const int tot = psum[NCH];
    const float4* __restrict__ W = (const float4*)g_W1T;

    float4 acc = make_float4(0.f, 0.f, 0.f, 0.f);
    int k = 0;
    for (; k + 4 <= tot; k += 4) {
        int i0 = sidx[k], i1 = sidx[k + 1], i2 = sidx[k + 2], i3 = sidx[k + 3];
        float4 w0 = W[(size_t)i0 * 128 + tid];
        float4 w1 = W[(size_t)i1 * 128 + tid];
        float4 w2 = W[(size_t)i2 * 128 + tid];
        float4 w3 = W[(size_t)i3 * 128 + tid];
        acc.x += w0.x; acc.y += w0.y; acc.z += w0.z; acc.w += w0.w;
        acc.x += w1.x; acc.y += w1.y; acc.z += w1.z; acc.w += w1.w;
        acc.x += w2.x; acc.y += w2.y; acc.z += w2.z; acc.w += w2.w;
        acc.x += w3.x; acc.y += w3.y; acc.z += w3.z; acc.w += w3.w;
    }
    for (; k < tot; k++) {
        float4 w0 = W[(size_t)sidx[k] * 128 + tid];
        acc.x += w0.x; acc.y += w0.y; acc.z += w0.z; acc.w += w0.w;
    }

    const int b = col / T_;
    const int t = col - b * T_;
    float4* dst = (float4*)(g_y1 + (size_t)t * R1 + b * NHID);
    dst[tid] = acc;   // 128 lanes x float4 = 2KB fully coalesced
}

// ---------------------------------------------------------------------------
// Scan v7: per-thread y row staged into shared memory in one coalesced burst
// (all LDGs independent -> latency amortized by MLP), then the sequential
// psp-IIR + exact-truncation-correction + refractory scan runs purely on
// affine LDS with spikes stored straight to global (off the dependency chain).
// No cross-thread sharing -> no syncs. One thread per row, 64 threads/block.
// ---------------------------------------------------------------------------
template<int STRIDE, bool TMAJOR_OUT>
__global__ __launch_bounds__(64) void iir_scan_kernel(
    const float* __restrict__ Y, float* __restrict__ Sout)
{
    extern __shared__ float ysm[];          // [T_][64]
    const int tid = threadIdx.x;
    const int row = blockIdx.x * 64 + tid;

    // burst stage-in: coalesced over rows, independent over t
    {
        const float* __restrict__ src = Y + row;
#pragma unroll 10
        for (int t = 0; t < T_; t++)
            ysm[t * 64 + tid] = src[(size_t)t * STRIDE];
    }

    const float* __restrict__ yc = ysm + tid;

    float P = 0.f, S = 0.f;       // psp states
    float P2 = 0.f, S2 = 0.f;     // delayed psp states
    float a = 0.f, bst = 0.f;     // refractory states

    // phase 1: t = 0..99 (no delayed input)
#pragma unroll 1
    for (int c = 0; c < 10; c++) {
#pragma unroll
        for (int k = 0; k < 10; k++) {
            const int t = c * 10 + k;
            const float yv = yc[t * 64];

            const float dP2 = D_SR * P2;          // delayed IIR ticks on zeros
            S2 = fmaf(D_SR, S2, dP2);
            P2 = dP2;
            const float corr = fmaf(-K2C, S2, -K3C * P2);

            const float dP = D_SR * P;
            S = fmaf(D_SR, S, dP);
            P = dP + yv;

            const float u = fmaf(C_E, S, fmaf(C_REF, bst, corr));
            const float s = (u >= THETA) ? 1.0f : 0.0f;
            const float g = D_REF * a;
            bst = fmaf(D_REF, bst, g);
            a   = g + s;

            if (TMAJOR_OUT) Sout[(size_t)t * STRIDE + row] = s;
            else            Sout[(size_t)row * T_ + t] = s;
        }
    }

    // phase 2: t = 100..349 (delayed input active)
#pragma unroll 1
    for (int c = 10; c < 35; c++) {
#pragma unroll
        for (int k = 0; k < 10; k++) {
            const int t = c * 10 + k;
            const float yv = yc[t * 64];
            const float yo = yc[(t - TK) * 64];

            const float dP2 = D_SR * P2;
            S2 = fmaf(D_SR, S2, dP2);
            P2 = dP2 + yo;
            const float corr = fmaf(-K2C, S2, -K3C * P2);

            const float dP = D_SR * P;
            S = fmaf(D_SR, S, dP);
            P = dP + yv;

            const float u = fmaf(C_E, S, fmaf(C_REF, bst, corr));
            const float s = (u >= THETA) ? 1.0f : 0.0f;
            const float g = D_REF * a;
            bst = fmaf(D_REF, bst, g);
            a   = g + s;

            if (TMAJOR_OUT) Sout[(size_t)t * STRIDE + row] = s;
            else            Sout[(size_t)row * T_ + t] = s;
        }
    }
}

// ---------------------------------------------------------------------------
// GEMM2 on t-major s1: warp per (b,t) column.
// ---------------------------------------------------------------------------
__global__ __launch_bounds__(256) void gemm2_kernel(
    const float* __restrict__ W2, const float* __restrict__ S1T,
    float* __restrict__ Z2T)
{
    __shared__ float w2s[NOUT * NHID];
    for (int i = threadIdx.x; i < NOUT * NHID; i += 256) w2s[i] = W2[i];
    __syncthreads();

    const int warp = threadIdx.x >> 5;
    const int lane = threadIdx.x & 31;
    const int col  = blockIdx.x * 8 + warp;
    const int b    = col / T_;
    const int t    = col - b * T_;

    const float4* __restrict__ sv = (const float4*)(S1T + (size_t)t * R1 + b * NHID);
    const float4* __restrict__ wv = (const float4*)w2s;

    float acc[NOUT];
#pragma unroll
    for (int j = 0; j < NOUT; j++) acc[j] = 0.0f;

#pragma unroll
    for (int p = 0; p < 4; p++) {
        float4 v = sv[p * 32 + lane];
#pragma unroll
        for (int j = 0; j < NOUT; j++) {
            float4 w = wv[j * 128 + p * 32 + lane];
            acc[j] += w.x * v.x + w.y * v.y + w.z * v.z + w.w * v.w;
        }
    }

#pragma unroll
    for (int j = 0; j < NOUT; j++) {
#pragma unroll
        for (int sh = 16; sh > 0; sh >>= 1)
            acc[j] += __shfl_xor_sync(0xffffffffu, acc[j], sh);
    }

    if (lane < NOUT)
        Z2T[(size_t)t * R2 + b * NOUT + lane] = acc[lane];
}

// ---------------------------------------------------------------------------
extern "C" void kernel_launch(void* const* d_in, const int* in_sizes, int n_in,
                              void* d_out, int out_size)
{
    const float* spikeInput = (const float*)d_in[0];  // [32, 2312, 350]
    const float* W1         = (const float*)d_in[1];  // [512, 2312]
    const float* W2         = (const float*)d_in[2];  // [10, 512]
    float*       out        = (float*)d_out;          // [32, 10, 350]

    float *y1p, *s1p, *z2p;
    cudaGetSymbolAddress((void**)&y1p, g_y1);
    cudaGetSymbolAddress((void**)&s1p, g_s1);
    cudaGetSymbolAddress((void**)&z2p, g_z2);

    const int scan_smem = T_ * 64 * (int)sizeof(float);   // 89.6 KB
    cudaFuncSetAttribute((const void*)iir_scan_kernel<R1, true>,
                         cudaFuncAttributeMaxDynamicSharedMemorySize, scan_smem);
    cudaFuncSetAttribute((const void*)iir_scan_kernel<R2, false>,
                         cudaFuncAttributeMaxDynamicSharedMemorySize, scan_smem);

    dim3 gt((NIN + 31) / 32, NHID / 32);      // (73, 16)
    transpose_w1_kernel<<<gt, 256>>>(W1);

    dim3 gb((T_ + 127) / 128, NCH, B_);       // (3, 8, 32)
    build_idx_kernel<<<gb, 128>>>(spikeInput);

    sparse_accum_kernel<<<NCOL, 128>>>();

    iir_scan_kernel<R1, true><<<R1 / 64, 64, scan_smem>>>(y1p, s1p);

    gemm2_kernel<<<NCOL / 8, 256>>>(W2, s1p, z2p);

    iir_scan_kernel<R2, false><<<R2 / 64, 64, scan_smem>>>(z2p, out);
}